// round 10
// baseline (speedup 1.0000x reference)
#include <cuda_runtime.h>
#include <cstddef>
#include <cstdint>

#define NN 50000
#define NE 800000
#define NG 512
#define HD 96
#define DHD 192
#define BN_EPS 1e-5f
#define SCAN_BLOCKS 49   // ceil(50000/1024)

// ---------------- scratch (device globals; no allocation allowed) ----------------
__device__ float g_z[NN * DHD];
__device__ float g_h[NN * HD];
__device__ float g_post[NN * HD];
__device__ float g_pooled[NG * HD];
__device__ float g_t1[NG * DHD];
__device__ float g_t2[NG * HD];
__device__ float g_sumS[8 * DHD];     // staged BN stats (8 stages)
__device__ float g_sumsqS[8 * DHD];
__device__ float g_counts[NG];
// CSR scratch
__device__ int g_deg[NN];
__device__ int g_rowptr[NN + 1];
__device__ int g_cursor[NN];
__device__ int g_srclist[NE];
__device__ int g_boff[64];

// ---------------- packed f32x2 helpers (sm_103a FFMA2 path) ----------------
__device__ __forceinline__ double ffma2(double a, double b, double c) {
    double r;
    asm("fma.rn.f32x2 %0, %1, %2, %3;" : "=d"(r) : "d"(a), "d"(b), "d"(c));
    return r;
}
__device__ __forceinline__ double dup2(float x) {
    double r;
    asm("mov.b64 %0, {%1, %1};" : "=d"(r) : "f"(x));
    return r;
}
__device__ __forceinline__ float2 unpack2(double v) {
    float2 r;
    asm("mov.b64 {%0, %1}, %2;" : "=f"(r.x), "=f"(r.y) : "d"(v));
    return r;
}
__device__ __forceinline__ double zero2() {
    double r;
    asm("mov.b64 %0, {%1, %1};" : "=d"(r) : "f"(0.0f));
    return r;
}

// inline BN scale/shift from staged raw sums
__device__ __forceinline__ void bn_coeff(int stage, int c, float invM,
                                         const float* __restrict__ gamma,
                                         const float* __restrict__ beta,
                                         float& sc, float& sh) {
    float mean = g_sumS[stage * DHD + c] * invM;
    float var = g_sumsqS[stage * DHD + c] * invM - mean * mean;
    sc = gamma[c] * rsqrtf(var + BN_EPS);
    sh = fmaf(-mean, sc, beta[c]);
}

// ---------------- fused init ----------------
__global__ void zero_all_kernel(float* __restrict__ out) {
    int i = blockIdx.x * blockDim.x + threadIdx.x;
    if (i < NN) g_deg[i] = 0;
    if (i < NG) g_counts[i] = 0.f;
    if (i < 8 * DHD) { g_sumS[i] = 0.f; g_sumsqS[i] = 0.f; }
    if (i < NG * HD) { g_pooled[i] = 0.f; out[i] = 0.f; }
}

__global__ void counts_hist_kernel(const int* __restrict__ batch,
                                   const int* __restrict__ dst) {
    int i = blockIdx.x * blockDim.x + threadIdx.x;
    if (i < NN) atomicAdd(&g_counts[batch[i]], 1.0f);
    if (i < NE) atomicAdd(&g_deg[dst[i]], 1);
}

// ---------------- CSR build ----------------
__global__ void scan1_kernel() {
    __shared__ int sh[1024];
    int i = blockIdx.x * 1024 + threadIdx.x;
    int v = (i < NN) ? g_deg[i] : 0;
    sh[threadIdx.x] = v;
    __syncthreads();
#pragma unroll
    for (int off = 1; off < 1024; off <<= 1) {
        int t = (threadIdx.x >= off) ? sh[threadIdx.x - off] : 0;
        __syncthreads();
        sh[threadIdx.x] += t;
        __syncthreads();
    }
    if (i < NN) g_cursor[i] = sh[threadIdx.x];
    if (threadIdx.x == 1023) g_boff[blockIdx.x] = sh[1023];
}

__global__ void scan3_kernel() {
    __shared__ int s_off;
    if (threadIdx.x == 0) {
        int run = 0;
        for (int b = 0; b < (int)blockIdx.x; b++) run += g_boff[b];
        s_off = run;
        if (blockIdx.x == SCAN_BLOCKS - 1) g_rowptr[NN] = run + g_boff[SCAN_BLOCKS - 1];
    }
    __syncthreads();
    int i = blockIdx.x * 1024 + threadIdx.x;
    if (i < NN) {
        int excl = g_cursor[i] - g_deg[i] + s_off;
        g_rowptr[i] = excl;
        g_cursor[i] = excl;
    }
}

__global__ void scatter_kernel(const int* __restrict__ src, const int* __restrict__ dst) {
    int i = blockIdx.x * blockDim.x + threadIdx.x;
    if (i < NE) {
        int d = dst[i];
        int p = atomicAdd(&g_cursor[d], 1);
        g_srclist[p] = src[i];
    }
}

// ---------------- fused agg + GEMM1: C[M,192] = agg(h)[M,96] @ B + bias ----------------
// TRANS 0: agg_i = h_i + sum_j h_j; TRANS 1: t(h) = relu(h*sc+sh)+vn applied per gathered row.
// Stats of C -> stage stOut. K=96, NC=192 fixed. Grid: 391 CTAs x 256 threads.
// Dynamic smem layout: Stg[128][100] | As[32][128] | Bs[32][64] | ssum[8][64] | ssq[8][64]
#define GA_SMEM (51200 + 16384 + 8192 + 2048 + 2048)
template <int TRANS>
__global__ void __launch_bounds__(256) gemmA_kernel(
    const float* __restrict__ h, const float* __restrict__ B,
    const float* __restrict__ bias, float* __restrict__ C,
    const float* __restrict__ gamma, const float* __restrict__ beta,
    const float* __restrict__ vn, int stIn, float invM, int stOut)
{
    extern __shared__ char smem[];
    float (*Stg)[100] = (float (*)[100])(smem);
    float (*As)[128]  = (float (*)[128])(smem + 51200);
    float (*Bs)[64]   = (float (*)[64])(smem + 51200 + 16384);
    float (*ssum)[64] = (float (*)[64])(smem + 51200 + 16384 + 8192);
    float (*ssq)[64]  = (float (*)[64])(smem + 51200 + 16384 + 8192 + 2048);

    int tid = threadIdx.x;
    int wid = tid >> 5;
    int lane = tid & 31;
    int r0 = blockIdx.x * 128;

    // ---- phase 1: gather (proven agg_csr / agg_bn loop, 16 nodes per warp) ----
    {
        bool active = lane < 24;
        const float4* hv = (const float4*)h;
        float4 sc4 = make_float4(0, 0, 0, 0), sh4 = sc4, vn4 = sc4;
        if (TRANS && active) {
            int f = lane * 4;
            bn_coeff(stIn, f + 0, invM, gamma, beta, sc4.x, sh4.x);
            bn_coeff(stIn, f + 1, invM, gamma, beta, sc4.y, sh4.y);
            bn_coeff(stIn, f + 2, invM, gamma, beta, sc4.z, sh4.z);
            bn_coeff(stIn, f + 3, invM, gamma, beta, sc4.w, sh4.w);
            vn4 = ((const float4*)vn)[lane];
        }
#define XF(v) do { if (TRANS) { \
        (v).x = fmaxf(fmaf((v).x, sc4.x, sh4.x), 0.f) + vn4.x; \
        (v).y = fmaxf(fmaf((v).y, sc4.y, sh4.y), 0.f) + vn4.y; \
        (v).z = fmaxf(fmaf((v).z, sc4.z, sh4.z), 0.f) + vn4.z; \
        (v).w = fmaxf(fmaf((v).w, sc4.w, sh4.w), 0.f) + vn4.w; } } while (0)
        for (int n = wid * 16; n < wid * 16 + 16; n++) {
            int node = r0 + n;
            float4 acc = make_float4(0.f, 0.f, 0.f, 0.f);
            if (node < NN) {
                int beg = g_rowptr[node];
                int end = g_rowptr[node + 1];
                if (active) { acc = hv[(size_t)node * 24 + lane]; XF(acc); }
                int e = beg;
                for (; e + 4 <= end; e += 4) {
                    int s0 = g_srclist[e + 0];
                    int s1 = g_srclist[e + 1];
                    int s2 = g_srclist[e + 2];
                    int s3 = g_srclist[e + 3];
                    if (active) {
                        float4 v0 = hv[(size_t)s0 * 24 + lane]; XF(v0);
                        float4 v1 = hv[(size_t)s1 * 24 + lane]; XF(v1);
                        float4 v2 = hv[(size_t)s2 * 24 + lane]; XF(v2);
                        float4 v3 = hv[(size_t)s3 * 24 + lane]; XF(v3);
                        acc.x += (v0.x + v1.x) + (v2.x + v3.x);
                        acc.y += (v0.y + v1.y) + (v2.y + v3.y);
                        acc.z += (v0.z + v1.z) + (v2.z + v3.z);
                        acc.w += (v0.w + v1.w) + (v2.w + v3.w);
                    }
                }
                for (; e < end; e++) {
                    int s = g_srclist[e];
                    if (active) {
                        float4 v = hv[(size_t)s * 24 + lane]; XF(v);
                        acc.x += v.x; acc.y += v.y; acc.z += v.z; acc.w += v.w;
                    }
                }
            }
            if (active) *(float4*)&Stg[n][lane * 4] = acc;
        }
#undef XF
    }
    __syncthreads();

    // ---- phase 2: FFMA2 GEMM over 3 N-chunks of 64, A from staging ----
    int tx = tid & 15;
    int ty = tid >> 4;
    for (int n0 = 0; n0 < DHD; n0 += 64) {
        double acc2[4][4];
#pragma unroll
        for (int ip = 0; ip < 4; ip++)
#pragma unroll
            for (int j = 0; j < 4; j++) acc2[ip][j] = zero2();

        for (int k0 = 0; k0 < HD; k0 += 32) {
#pragma unroll
            for (int i = 0; i < 4; i++) {
                int idx4 = tid + i * 256;
                int row = idx4 >> 3;
                int kk  = (idx4 & 7) << 2;
                float4 v = *(const float4*)&Stg[row][k0 + kk];
                As[kk + 0][row] = v.x;
                As[kk + 1][row] = v.y;
                As[kk + 2][row] = v.z;
                As[kk + 3][row] = v.w;
            }
#pragma unroll
            for (int t = tid; t < 8 * 64; t += 256) {
                int row = t >> 4;
                int cc  = (t & 15) << 2;
                *(float4*)&Bs[row][cc] =
                    *(const float4*)(B + (size_t)(k0 + row) * DHD + n0 + cc);
            }
            __syncthreads();
#pragma unroll
            for (int kk = 0; kk < 32; kk++) {
                double2 aL = *(const double2*)&As[kk][ty * 8];
                double2 aH = *(const double2*)&As[kk][ty * 8 + 4];
                double a2[4] = {aL.x, aL.y, aH.x, aH.y};
                float4 b = *(const float4*)&Bs[kk][tx * 4];
                double bd[4] = {dup2(b.x), dup2(b.y), dup2(b.z), dup2(b.w)};
#pragma unroll
                for (int ip = 0; ip < 4; ip++)
#pragma unroll
                    for (int j = 0; j < 4; j++)
                        acc2[ip][j] = ffma2(a2[ip], bd[j], acc2[ip][j]);
            }
            __syncthreads();
        }

        float bb[4];
#pragma unroll
        for (int j = 0; j < 4; j++) bb[j] = bias[n0 + tx * 4 + j];

        float s[4] = {0.f, 0.f, 0.f, 0.f};
        float q[4] = {0.f, 0.f, 0.f, 0.f};
#pragma unroll
        for (int r = 0; r < 8; r++) {
            int gr = r0 + ty * 8 + r;
            if (gr < NN) {
                int ip = r >> 1;
                float v[4];
#pragma unroll
                for (int j = 0; j < 4; j++) {
                    float2 u = unpack2(acc2[ip][j]);
                    float c = ((r & 1) ? u.y : u.x) + bb[j];
                    v[j] = c;
                    s[j] += c; q[j] = fmaf(c, c, q[j]);
                }
                *(float4*)(C + (size_t)gr * DHD + n0 + tx * 4) =
                    make_float4(v[0], v[1], v[2], v[3]);
            }
        }
#pragma unroll
        for (int j = 0; j < 4; j++) {
            s[j] += __shfl_xor_sync(0xFFFFFFFFu, s[j], 16);
            q[j] += __shfl_xor_sync(0xFFFFFFFFu, q[j], 16);
        }
        if ((tid & 15) == 0) {
            int w = tid >> 5;
            (void)w;
        }
        {
            int w = tid >> 5;
            int lane2 = tid & 31;
            if (lane2 < 16) {
#pragma unroll
                for (int j = 0; j < 4; j++) {
                    ssum[w][lane2 * 4 + j] = s[j];
                    ssq[w][lane2 * 4 + j] = q[j];
                }
            }
            __syncthreads();
            if (tid < 64) {
                float a = 0.f, b2 = 0.f;
#pragma unroll
                for (int w2 = 0; w2 < 8; w2++) { a += ssum[w2][tid]; b2 += ssq[w2][tid]; }
                atomicAdd(&g_sumS[stOut * DHD + n0 + tid], a);
                atomicAdd(&g_sumsqS[stOut * DHD + n0 + tid], b2);
            }
            __syncthreads();
        }
    }
}

// ---------------- FFMA2 GEMM (GEMM2s + vmlp; static smem; proven R7 core) ----------------
// AMODE 0: A as-is; 2: relu(A*sc+sh) from stage stIn; 3: A + addrow[k]
template <int AMODE, int TN>
__global__ void __launch_bounds__(256) gemm2_kernel(
    const float* __restrict__ A,
    const float* __restrict__ B, const float* __restrict__ bias,
    float* __restrict__ C, int M, int K, int NC,
    const float* __restrict__ gamma, const float* __restrict__ beta,
    int stIn, float invMin, int stOut, const float* __restrict__ addrow)
{
    constexpr int BN = TN * 16;
    __shared__ float As[32][128];
    __shared__ float Bs[32][BN];
    __shared__ float ssum[8][BN];
    __shared__ float ssq[8][BN];
    __shared__ float Ssc[DHD];
    __shared__ float Ssh[DHD];

    int tid = threadIdx.x;
    int tx = tid & 15;
    int ty = tid >> 4;
    int r0 = blockIdx.x * 128;
    int n0 = blockIdx.y * BN;

    if (AMODE == 2) {
        for (int c = tid; c < K; c += 256)
            bn_coeff(stIn, c, invMin, gamma, beta, Ssc[c], Ssh[c]);
        __syncthreads();
    }

    double acc2[4][TN];
#pragma unroll
    for (int ip = 0; ip < 4; ip++)
#pragma unroll
        for (int j = 0; j < TN; j++) acc2[ip][j] = zero2();

    for (int k0 = 0; k0 < K; k0 += 32) {
#pragma unroll
        for (int i = 0; i < 4; i++) {
            int idx4 = tid + i * 256;
            int row = idx4 >> 3;
            int kk  = (idx4 & 7) << 2;
            float4 v = make_float4(0.f, 0.f, 0.f, 0.f);
            int gr = r0 + row;
            if (gr < M) {
                v = *(const float4*)(A + (size_t)gr * K + k0 + kk);
                int kc = k0 + kk;
                if (AMODE == 2) {
                    v.x = fmaxf(fmaf(v.x, Ssc[kc + 0], Ssh[kc + 0]), 0.f);
                    v.y = fmaxf(fmaf(v.y, Ssc[kc + 1], Ssh[kc + 1]), 0.f);
                    v.z = fmaxf(fmaf(v.z, Ssc[kc + 2], Ssh[kc + 2]), 0.f);
                    v.w = fmaxf(fmaf(v.w, Ssc[kc + 3], Ssh[kc + 3]), 0.f);
                } else if (AMODE == 3) {
                    v.x += addrow[kc + 0];
                    v.y += addrow[kc + 1];
                    v.z += addrow[kc + 2];
                    v.w += addrow[kc + 3];
                }
            }
            As[kk + 0][row] = v.x;
            As[kk + 1][row] = v.y;
            As[kk + 2][row] = v.z;
            As[kk + 3][row] = v.w;
        }
#pragma unroll
        for (int t = tid; t < 8 * BN; t += 256) {
            int row = t / (BN / 4);
            int cc  = (t % (BN / 4)) << 2;
            *(float4*)&Bs[row][cc] =
                *(const float4*)(B + (size_t)(k0 + row) * NC + n0 + cc);
        }
        __syncthreads();
#pragma unroll
        for (int kk = 0; kk < 32; kk++) {
            double2 aL = *(const double2*)&As[kk][ty * 8];
            double2 aH = *(const double2*)&As[kk][ty * 8 + 4];
            double a2[4] = {aL.x, aL.y, aH.x, aH.y};
            double bd[TN];
            if (TN == 4) {
                float4 b = *(const float4*)&Bs[kk][tx * 4];
                bd[0] = dup2(b.x); bd[1] = dup2(b.y);
                bd[2] = dup2(b.z); bd[3] = dup2(b.w);
            } else {
                float2 b = *(const float2*)&Bs[kk][tx * 2];
                bd[0] = dup2(b.x); bd[1] = dup2(b.y);
            }
#pragma unroll
            for (int ip = 0; ip < 4; ip++)
#pragma unroll
                for (int j = 0; j < TN; j++)
                    acc2[ip][j] = ffma2(a2[ip], bd[j], acc2[ip][j]);
        }
        __syncthreads();
    }

    float bb[TN];
#pragma unroll
    for (int j = 0; j < TN; j++) bb[j] = bias[n0 + tx * TN + j];

    float s[TN], q[TN];
#pragma unroll
    for (int j = 0; j < TN; j++) { s[j] = 0.f; q[j] = 0.f; }

#pragma unroll
    for (int r = 0; r < 8; r++) {
        int gr = r0 + ty * 8 + r;
        if (gr < M) {
            int ip = r >> 1;
            float v[TN];
#pragma unroll
            for (int j = 0; j < TN; j++) {
                float2 u = unpack2(acc2[ip][j]);
                float c = ((r & 1) ? u.y : u.x) + bb[j];
                v[j] = c;
                s[j] += c; q[j] = fmaf(c, c, q[j]);
            }
            float* cp = C + (size_t)gr * NC + n0 + tx * TN;
            if (TN == 4) *(float4*)cp = make_float4(v[0], v[1], v[2], v[3]);
            else         *(float2*)cp = make_float2(v[0], v[1]);
        }
    }

    {
#pragma unroll
        for (int j = 0; j < TN; j++) {
            s[j] += __shfl_xor_sync(0xFFFFFFFFu, s[j], 16);
            q[j] += __shfl_xor_sync(0xFFFFFFFFu, q[j], 16);
        }
        int w = tid >> 5;
        int lane = tid & 31;
        if (lane < 16) {
#pragma unroll
            for (int j = 0; j < TN; j++) {
                ssum[w][lane * TN + j] = s[j];
                ssq[w][lane * TN + j] = q[j];
            }
        }
        __syncthreads();
        if (tid < BN) {
            float a = 0.f, b2 = 0.f;
#pragma unroll
            for (int w2 = 0; w2 < 8; w2++) { a += ssum[w2][tid]; b2 += ssq[w2][tid]; }
            atomicAdd(&g_sumS[stOut * DHD + n0 + tid], a);
            atomicAdd(&g_sumsqS[stOut * DHD + n0 + tid], b2);
        }
    }
}

// ---------------- fused elementwise stages ----------------
__global__ void post2_kernel(const int* __restrict__ batch,
                             const float* __restrict__ gamma,
                             const float* __restrict__ beta,
                             int stage, float invM) {
    int node = blockIdx.x * blockDim.y + threadIdx.y;
    if (node >= NN) return;
    int f = threadIdx.x;
    float sc, sh;
    bn_coeff(stage, f, invM, gamma, beta, sc, sh);
    size_t idx = (size_t)node * HD + f;
    float p = fmaxf(fmaf(g_h[idx], sc, sh), 0.f);
    g_post[idx] = p;
    atomicAdd(&g_pooled[batch[node] * HD + f], p);
}

__global__ void post3_kernel(const int* __restrict__ batch,
                             const float* __restrict__ gamma,
                             const float* __restrict__ beta,
                             int stage, float invM) {
    int node = blockIdx.x * blockDim.y + threadIdx.y;
    if (node >= NN) return;
    int f = threadIdx.x;
    float sc, sh;
    bn_coeff(stage, f, invM, gamma, beta, sc, sh);
    size_t idx = (size_t)node * HD + f;
    float v = g_t2[batch[node] * HD + f];
    g_post[idx] += fmaxf(fmaf(v, sc, sh), 0.f);
}

__global__ void readout_kernel(const int* __restrict__ batch,
                               const float* __restrict__ gamma,
                               const float* __restrict__ beta,
                               int stage, float invM, float* __restrict__ out) {
    int node = blockIdx.x * blockDim.y + threadIdx.y;
    if (node >= NN) return;
    int f = threadIdx.x;
    float sc, sh;
    bn_coeff(stage, f, invM, gamma, beta, sc, sh);
    size_t idx = (size_t)node * HD + f;
    atomicAdd(&out[batch[node] * HD + f], fmaf(g_h[idx], sc, sh));
}

__global__ void div_kernel(float* __restrict__ out) {
    int i = blockIdx.x * blockDim.x + threadIdx.x;
    if (i < NG * HD) out[i] /= fmaxf(g_counts[i / HD], 1.0f);
}

// ---------------- launch ----------------
extern "C" void kernel_launch(void* const* d_in, const int* in_sizes, int n_in,
                              void* d_out, int out_size) {
    const float* x      = (const float*)d_in[0];
    const int*   edge   = (const int*)d_in[1];
    const int*   batch  = (const int*)d_in[2];
    const float* vn     = (const float*)d_in[4];
    const float* c1_W1  = (const float*)d_in[5];
    const float* c1_b1  = (const float*)d_in[6];
    const float* c1_g1  = (const float*)d_in[7];
    const float* c1_be1 = (const float*)d_in[8];
    const float* c1_W2  = (const float*)d_in[9];
    const float* c1_b2  = (const float*)d_in[10];
    const float* bn1_g  = (const float*)d_in[11];
    const float* bn1_b  = (const float*)d_in[12];
    const float* cs_W1  = (const float*)d_in[13];
    const float* cs_b1  = (const float*)d_in[14];
    const float* cs_g1  = (const float*)d_in[15];
    const float* cs_be1 = (const float*)d_in[16];
    const float* cs_W2  = (const float*)d_in[17];
    const float* cs_b2  = (const float*)d_in[18];
    const float* bns_g  = (const float*)d_in[19];
    const float* bns_b  = (const float*)d_in[20];
    const float* vm_W1  = (const float*)d_in[21];
    const float* vm_b1  = (const float*)d_in[22];
    const float* vm_g1  = (const float*)d_in[23];
    const float* vm_be1 = (const float*)d_in[24];
    const float* vm_W2  = (const float*)d_in[25];
    const float* vm_b2  = (const float*)d_in[26];
    const float* vm_g2  = (const float*)d_in[27];
    const float* vm_be2 = (const float*)d_in[28];
    float* out = (float*)d_out;

    const int* src = edge;
    const int* dst = edge + NE;

    float *p_z, *p_h, *p_post, *p_pooled, *p_t1, *p_t2;
    cudaGetSymbolAddress((void**)&p_z, g_z);
    cudaGetSymbolAddress((void**)&p_h, g_h);
    cudaGetSymbolAddress((void**)&p_post, g_post);
    cudaGetSymbolAddress((void**)&p_pooled, g_pooled);
    cudaGetSymbolAddress((void**)&p_t1, g_t1);
    cudaGetSymbolAddress((void**)&p_t2, g_t2);

    cudaFuncSetAttribute(gemmA_kernel<0>, cudaFuncAttributeMaxDynamicSharedMemorySize, GA_SMEM);
    cudaFuncSetAttribute(gemmA_kernel<1>, cudaFuncAttributeMaxDynamicSharedMemorySize, GA_SMEM);

    dim3 ew(96, 4);
    int ewg = (NN + 3) / 4;
    const float invN = 1.0f / (float)NN;
    const float invG = 1.0f / (float)NG;
    int gaGrid = (NN + 127) / 128;   // 391

    auto g32 = [](int M) { return dim3((M + 127) / 128, HD / 32); };   // TN=2 (NC=96)

    // ---- init + CSR build ----
    zero_all_kernel<<<SCAN_BLOCKS, 1024>>>(out);
    counts_hist_kernel<<<(NE + 255) / 256, 256>>>(batch, dst);
    scan1_kernel<<<SCAN_BLOCKS, 1024>>>();
    scan3_kernel<<<SCAN_BLOCKS, 1024>>>();
    scatter_kernel<<<(NE + 255) / 256, 256>>>(src, dst);

    // ---- layer 1 (agg fused into GEMM1); stats stages 0 (z1), 1 (h1) ----
    gemmA_kernel<0><<<gaGrid, 256, GA_SMEM>>>(x, c1_W1, c1_b1, p_z,
                                              nullptr, nullptr, nullptr, 0, 0.f, 0);
    gemm2_kernel<2, 2><<<g32(NN), 256>>>(p_z, c1_W2, c1_b2, p_h, NN, DHD, HD,
                                         c1_g1, c1_be1, 0, invN, 1, nullptr);

    // ---- layer 2 (bn+vn transform fused into gather); stages 2 (z2), 3 (h2) ----
    gemmA_kernel<1><<<gaGrid, 256, GA_SMEM>>>(p_h, cs_W1, cs_b1, p_z,
                                              bn1_g, bn1_b, vn, 1, invN, 2);
    gemm2_kernel<2, 2><<<g32(NN), 256>>>(p_z, cs_W2, cs_b2, p_h, NN, DHD, HD,
                                         cs_g1, cs_be1, 2, invN, 3, nullptr);
    post2_kernel<<<ewg, ew>>>(batch, bns_g, bns_b, 3, invN);

    // ---- virtual node MLP; stages 4 (t1), 5 (t2) ----
    gemm2_kernel<3, 4><<<dim3(4, 3), 256>>>(p_pooled, vm_W1, vm_b1, p_t1, NG, HD, DHD,
                                            nullptr, nullptr, 0, 0.f, 4, vn);
    gemm2_kernel<2, 2><<<dim3(4, 3), 256>>>(p_t1, vm_W2, vm_b2, p_t2, NG, DHD, HD,
                                            vm_g1, vm_be1, 4, invG, 5, nullptr);
    post3_kernel<<<ewg, ew>>>(batch, vm_g2, vm_be2, 5, invG);

    // ---- layer 3; stages 6 (z3), 7 (h3) ----
    gemmA_kernel<0><<<gaGrid, 256, GA_SMEM>>>(p_post, cs_W1 + HD * DHD, cs_b1 + DHD, p_z,
                                              nullptr, nullptr, nullptr, 0, 0.f, 6);
    gemm2_kernel<2, 2><<<g32(NN), 256>>>(p_z, cs_W2 + DHD * HD, cs_b2 + HD, p_h, NN, DHD, HD,
                                         cs_g1 + DHD, cs_be1 + DHD, 6, invN, 7, nullptr);

    // ---- mean-pool readout ----
    readout_kernel<<<ewg, ew>>>(batch, bns_g + HD, bns_b + HD, 7, invN, out);
    div_kernel<<<(NG * HD + 255) / 256, 256>>>(out);
}

// round 12
// speedup vs baseline: 1.3728x; 1.3728x over previous
#include <cuda_runtime.h>
#include <cstddef>
#include <cstdint>

#define NN 50000
#define NE 800000
#define NG 512
#define HD 96
#define DHD 192
#define BN_EPS 1e-5f
#define SCAN_BLOCKS 49   // ceil(50000/1024)

// ---------------- scratch (device globals; no allocation allowed) ----------------
__device__ float g_agg[NN * HD];
__device__ float g_z[NN * DHD];
__device__ float g_h[NN * HD];
__device__ float g_post[NN * HD];
__device__ float g_pooled[NG * HD];
__device__ float g_t1[NG * DHD];
__device__ float g_t2[NG * HD];
__device__ float g_sumS[8 * DHD];     // staged BN stats (8 stages)
__device__ float g_sumsqS[8 * DHD];
__device__ float g_counts[NG];
// CSR scratch
__device__ int g_deg[NN];
__device__ int g_rowptr[NN + 1];
__device__ int g_cursor[NN];
__device__ int g_srclist[NE];
__device__ int g_boff[64];

// ---------------- packed f32x2 helpers (sm_103a FFMA2 path) ----------------
__device__ __forceinline__ double ffma2(double a, double b, double c) {
    double r;
    asm("fma.rn.f32x2 %0, %1, %2, %3;" : "=d"(r) : "d"(a), "d"(b), "d"(c));
    return r;
}
__device__ __forceinline__ double dup2(float x) {
    double r;
    asm("mov.b64 %0, {%1, %1};" : "=d"(r) : "f"(x));
    return r;
}
__device__ __forceinline__ float2 unpack2(double v) {
    float2 r;
    asm("mov.b64 {%0, %1}, %2;" : "=f"(r.x), "=f"(r.y) : "d"(v));
    return r;
}
__device__ __forceinline__ double zero2() {
    double r;
    asm("mov.b64 %0, {%1, %1};" : "=d"(r) : "f"(0.0f));
    return r;
}

// inline BN scale/shift from staged raw sums
__device__ __forceinline__ void bn_coeff(int stage, int c, float invM,
                                         const float* __restrict__ gamma,
                                         const float* __restrict__ beta,
                                         float& sc, float& sh) {
    float mean = g_sumS[stage * DHD + c] * invM;
    float var = g_sumsqS[stage * DHD + c] * invM - mean * mean;
    sc = gamma[c] * rsqrtf(var + BN_EPS);
    sh = fmaf(-mean, sc, beta[c]);
}

// ---------------- fused init ----------------
__global__ void zero_all_kernel(float* __restrict__ out) {
    int i = blockIdx.x * blockDim.x + threadIdx.x;
    if (i < NN) g_deg[i] = 0;
    if (i < NG) g_counts[i] = 0.f;
    if (i < 8 * DHD) { g_sumS[i] = 0.f; g_sumsqS[i] = 0.f; }
    if (i < NG * HD) { g_pooled[i] = 0.f; out[i] = 0.f; }
}

__global__ void counts_hist_kernel(const int* __restrict__ batch,
                                   const int* __restrict__ dst) {
    int i = blockIdx.x * blockDim.x + threadIdx.x;
    if (i < NN) atomicAdd(&g_counts[batch[i]], 1.0f);
    if (i < NE) atomicAdd(&g_deg[dst[i]], 1);
}

// ---------------- CSR build ----------------
__global__ void scan1_kernel() {
    __shared__ int sh[1024];
    int i = blockIdx.x * 1024 + threadIdx.x;
    int v = (i < NN) ? g_deg[i] : 0;
    sh[threadIdx.x] = v;
    __syncthreads();
#pragma unroll
    for (int off = 1; off < 1024; off <<= 1) {
        int t = (threadIdx.x >= off) ? sh[threadIdx.x - off] : 0;
        __syncthreads();
        sh[threadIdx.x] += t;
        __syncthreads();
    }
    if (i < NN) g_cursor[i] = sh[threadIdx.x];
    if (threadIdx.x == 1023) g_boff[blockIdx.x] = sh[1023];
}

__global__ void scan3_kernel() {
    __shared__ int s_off;
    if (threadIdx.x == 0) {
        int run = 0;
        for (int b = 0; b < (int)blockIdx.x; b++) run += g_boff[b];
        s_off = run;
        if (blockIdx.x == SCAN_BLOCKS - 1) g_rowptr[NN] = run + g_boff[SCAN_BLOCKS - 1];
    }
    __syncthreads();
    int i = blockIdx.x * 1024 + threadIdx.x;
    if (i < NN) {
        int excl = g_cursor[i] - g_deg[i] + s_off;
        g_rowptr[i] = excl;
        g_cursor[i] = excl;
    }
}

__global__ void scatter_kernel(const int* __restrict__ src, const int* __restrict__ dst) {
    int i = blockIdx.x * blockDim.x + threadIdx.x;
    if (i < NE) {
        int d = dst[i];
        int p = atomicAdd(&g_cursor[d], 1);
        g_srclist[p] = src[i];
    }
}

// ---------------- CSR aggregation (warp per node, float4 gathers) ----------------
__global__ void __launch_bounds__(256) agg_csr_kernel(const float* __restrict__ h) {
    int node = (blockIdx.x * 256 + threadIdx.x) >> 5;
    if (node >= NN) return;
    int lane = threadIdx.x & 31;
    bool active = lane < 24;
    const float4* hv = (const float4*)h;
    int beg = g_rowptr[node];
    int end = g_rowptr[node + 1];
    float4 acc = make_float4(0.f, 0.f, 0.f, 0.f);
    if (active) acc = hv[(size_t)node * 24 + lane];
    int e = beg;
    for (; e + 4 <= end; e += 4) {
        int s0 = g_srclist[e + 0];
        int s1 = g_srclist[e + 1];
        int s2 = g_srclist[e + 2];
        int s3 = g_srclist[e + 3];
        if (active) {
            float4 v0 = hv[(size_t)s0 * 24 + lane];
            float4 v1 = hv[(size_t)s1 * 24 + lane];
            float4 v2 = hv[(size_t)s2 * 24 + lane];
            float4 v3 = hv[(size_t)s3 * 24 + lane];
            acc.x += (v0.x + v1.x) + (v2.x + v3.x);
            acc.y += (v0.y + v1.y) + (v2.y + v3.y);
            acc.z += (v0.z + v1.z) + (v2.z + v3.z);
            acc.w += (v0.w + v1.w) + (v2.w + v3.w);
        }
    }
    for (; e < end; e++) {
        int s = g_srclist[e];
        if (active) {
            float4 v = hv[(size_t)s * 24 + lane];
            acc.x += v.x; acc.y += v.y; acc.z += v.z; acc.w += v.w;
        }
    }
    if (active) ((float4*)g_agg)[(size_t)node * 24 + lane] = acc;
}

// transform-on-gather: t(h) = relu(h*sc+sh) + vn[f]
__global__ void __launch_bounds__(256) agg_bn_kernel(
    const float* __restrict__ h, const float* __restrict__ gamma,
    const float* __restrict__ beta, const float* __restrict__ vn,
    int stage, float invM)
{
    int node = (blockIdx.x * 256 + threadIdx.x) >> 5;
    if (node >= NN) return;
    int lane = threadIdx.x & 31;
    bool active = lane < 24;
    const float4* hv = (const float4*)h;

    float4 sc4 = make_float4(0, 0, 0, 0), sh4 = sc4, vn4 = sc4;
    if (active) {
        int f = lane * 4;
        bn_coeff(stage, f + 0, invM, gamma, beta, sc4.x, sh4.x);
        bn_coeff(stage, f + 1, invM, gamma, beta, sc4.y, sh4.y);
        bn_coeff(stage, f + 2, invM, gamma, beta, sc4.z, sh4.z);
        bn_coeff(stage, f + 3, invM, gamma, beta, sc4.w, sh4.w);
        vn4 = ((const float4*)vn)[lane];
    }
#define XFORM(v) do { \
        (v).x = fmaxf(fmaf((v).x, sc4.x, sh4.x), 0.f) + vn4.x; \
        (v).y = fmaxf(fmaf((v).y, sc4.y, sh4.y), 0.f) + vn4.y; \
        (v).z = fmaxf(fmaf((v).z, sc4.z, sh4.z), 0.f) + vn4.z; \
        (v).w = fmaxf(fmaf((v).w, sc4.w, sh4.w), 0.f) + vn4.w; } while (0)

    int beg = g_rowptr[node];
    int end = g_rowptr[node + 1];
    float4 acc = make_float4(0.f, 0.f, 0.f, 0.f);
    if (active) { acc = hv[(size_t)node * 24 + lane]; XFORM(acc); }
    int e = beg;
    for (; e + 4 <= end; e += 4) {
        int s0 = g_srclist[e + 0];
        int s1 = g_srclist[e + 1];
        int s2 = g_srclist[e + 2];
        int s3 = g_srclist[e + 3];
        if (active) {
            float4 v0 = hv[(size_t)s0 * 24 + lane]; XFORM(v0);
            float4 v1 = hv[(size_t)s1 * 24 + lane]; XFORM(v1);
            float4 v2 = hv[(size_t)s2 * 24 + lane]; XFORM(v2);
            float4 v3 = hv[(size_t)s3 * 24 + lane]; XFORM(v3);
            acc.x += (v0.x + v1.x) + (v2.x + v3.x);
            acc.y += (v0.y + v1.y) + (v2.y + v3.y);
            acc.z += (v0.z + v1.z) + (v2.z + v3.z);
            acc.w += (v0.w + v1.w) + (v2.w + v3.w);
        }
    }
    for (; e < end; e++) {
        int s = g_srclist[e];
        if (active) {
            float4 v = hv[(size_t)s * 24 + lane]; XFORM(v);
            acc.x += v.x; acc.y += v.y; acc.z += v.z; acc.w += v.w;
        }
    }
    if (active) ((float4*)g_agg)[(size_t)node * 24 + lane] = acc;
#undef XFORM
}

// ---------------- FFMA2 tiled GEMM (v1 core; TN=2/4/6) ----------------
// AMODE 0: A as-is; 2: relu(A*sc+sh) from stage stIn; 3: A + addrow[k]
// Stats of C accumulate into stage stOut.
template <int AMODE, int TN>
__global__ void __launch_bounds__(256) gemm2_kernel(
    const float* __restrict__ A,
    const float* __restrict__ B, const float* __restrict__ bias,
    float* __restrict__ C, int M, int K, int NC,
    const float* __restrict__ gamma, const float* __restrict__ beta,
    int stIn, float invMin, int stOut, const float* __restrict__ addrow)
{
    constexpr int BN = TN * 16;
    __shared__ float As[32][128];
    __shared__ float Bs[32][BN];
    __shared__ float ssum[8][BN];
    __shared__ float ssq[8][BN];
    __shared__ float Ssc[DHD];
    __shared__ float Ssh[DHD];

    int tid = threadIdx.x;
    int tx = tid & 15;
    int ty = tid >> 4;
    int r0 = blockIdx.x * 128;
    int n0 = blockIdx.y * BN;

    if (AMODE == 2) {
        for (int c = tid; c < K; c += 256)
            bn_coeff(stIn, c, invMin, gamma, beta, Ssc[c], Ssh[c]);
        __syncthreads();
    }

    double acc2[4][TN];
#pragma unroll
    for (int ip = 0; ip < 4; ip++)
#pragma unroll
        for (int j = 0; j < TN; j++) acc2[ip][j] = zero2();

    for (int k0 = 0; k0 < K; k0 += 32) {
#pragma unroll
        for (int i = 0; i < 4; i++) {
            int idx4 = tid + i * 256;
            int row = idx4 >> 3;
            int kk  = (idx4 & 7) << 2;
            float4 v = make_float4(0.f, 0.f, 0.f, 0.f);
            int gr = r0 + row;
            if (gr < M) {
                v = *(const float4*)(A + (size_t)gr * K + k0 + kk);
                int kc = k0 + kk;
                if (AMODE == 2) {
                    v.x = fmaxf(fmaf(v.x, Ssc[kc + 0], Ssh[kc + 0]), 0.f);
                    v.y = fmaxf(fmaf(v.y, Ssc[kc + 1], Ssh[kc + 1]), 0.f);
                    v.z = fmaxf(fmaf(v.z, Ssc[kc + 2], Ssh[kc + 2]), 0.f);
                    v.w = fmaxf(fmaf(v.w, Ssc[kc + 3], Ssh[kc + 3]), 0.f);
                } else if (AMODE == 3) {
                    v.x += addrow[kc + 0];
                    v.y += addrow[kc + 1];
                    v.z += addrow[kc + 2];
                    v.w += addrow[kc + 3];
                }
            }
            As[kk + 0][row] = v.x;
            As[kk + 1][row] = v.y;
            As[kk + 2][row] = v.z;
            As[kk + 3][row] = v.w;
        }
#pragma unroll
        for (int t = tid; t < 8 * BN; t += 256) {
            int row = t / (BN / 4);
            int cc  = (t % (BN / 4)) << 2;
            *(float4*)&Bs[row][cc] =
                *(const float4*)(B + (size_t)(k0 + row) * NC + n0 + cc);
        }
        __syncthreads();
#pragma unroll
        for (int kk = 0; kk < 32; kk++) {
            double2 aL = *(const double2*)&As[kk][ty * 8];
            double2 aH = *(const double2*)&As[kk][ty * 8 + 4];
            double a2[4] = {aL.x, aL.y, aH.x, aH.y};
            double bd[TN];
            if (TN == 4) {
                float4 b = *(const float4*)&Bs[kk][tx * 4];
                bd[0] = dup2(b.x); bd[1] = dup2(b.y);
                bd[2] = dup2(b.z); bd[3] = dup2(b.w);
            } else if (TN == 2) {
                float2 b = *(const float2*)&Bs[kk][tx * 2];
                bd[0] = dup2(b.x); bd[1] = dup2(b.y);
            } else {  // TN == 6
                float2 b0 = *(const float2*)&Bs[kk][tx * 6];
                float2 b1 = *(const float2*)&Bs[kk][tx * 6 + 2];
                float2 b2 = *(const float2*)&Bs[kk][tx * 6 + 4];
                bd[0] = dup2(b0.x); bd[1] = dup2(b0.y);
                bd[2] = dup2(b1.x); bd[3] = dup2(b1.y);
                bd[4] = dup2(b2.x); bd[5] = dup2(b2.y);
            }
#pragma unroll
            for (int ip = 0; ip < 4; ip++)
#pragma unroll
                for (int j = 0; j < TN; j++)
                    acc2[ip][j] = ffma2(a2[ip], bd[j], acc2[ip][j]);
        }
        __syncthreads();
    }

    float bb[TN];
#pragma unroll
    for (int j = 0; j < TN; j++) bb[j] = bias[n0 + tx * TN + j];

    float s[TN], q[TN];
#pragma unroll
    for (int j = 0; j < TN; j++) { s[j] = 0.f; q[j] = 0.f; }

#pragma unroll
    for (int r = 0; r < 8; r++) {
        int gr = r0 + ty * 8 + r;
        if (gr < M) {
            int ip = r >> 1;
            float v[TN];
#pragma unroll
            for (int j = 0; j < TN; j++) {
                float2 u = unpack2(acc2[ip][j]);
                float c = ((r & 1) ? u.y : u.x) + bb[j];
                v[j] = c;
                s[j] += c; q[j] = fmaf(c, c, q[j]);
            }
            float* cp = C + (size_t)gr * NC + n0 + tx * TN;
            if (TN == 4) {
                *(float4*)cp = make_float4(v[0], v[1], v[2], v[3]);
            } else if (TN == 2) {
                *(float2*)cp = make_float2(v[0], v[1]);
            } else {  // TN == 6
                *(float2*)(cp + 0) = make_float2(v[0], v[1]);
                *(float2*)(cp + 2) = make_float2(v[2], v[3]);
                *(float2*)(cp + 4) = make_float2(v[4], v[5]);
            }
        }
    }

    {
#pragma unroll
        for (int j = 0; j < TN; j++) {
            s[j] += __shfl_xor_sync(0xFFFFFFFFu, s[j], 16);
            q[j] += __shfl_xor_sync(0xFFFFFFFFu, q[j], 16);
        }
        int w = tid >> 5;
        int lane = tid & 31;
        if (lane < 16) {
#pragma unroll
            for (int j = 0; j < TN; j++) {
                ssum[w][lane * TN + j] = s[j];
                ssq[w][lane * TN + j] = q[j];
            }
        }
        __syncthreads();
        if (tid < BN) {
            float a = 0.f, b2 = 0.f;
#pragma unroll
            for (int w2 = 0; w2 < 8; w2++) { a += ssum[w2][tid]; b2 += ssq[w2][tid]; }
            atomicAdd(&g_sumS[stOut * DHD + n0 + tid], a);
            atomicAdd(&g_sumsqS[stOut * DHD + n0 + tid], b2);
        }
    }
}

// ---------------- fused elementwise stages ----------------
__global__ void post2_kernel(const int* __restrict__ batch,
                             const float* __restrict__ gamma,
                             const float* __restrict__ beta,
                             int stage, float invM) {
    int node = blockIdx.x * blockDim.y + threadIdx.y;
    if (node >= NN) return;
    int f = threadIdx.x;
    float sc, sh;
    bn_coeff(stage, f, invM, gamma, beta, sc, sh);
    size_t idx = (size_t)node * HD + f;
    float p = fmaxf(fmaf(g_h[idx], sc, sh), 0.f);
    g_post[idx] = p;
    atomicAdd(&g_pooled[batch[node] * HD + f], p);
}

__global__ void post3_kernel(const int* __restrict__ batch,
                             const float* __restrict__ gamma,
                             const float* __restrict__ beta,
                             int stage, float invM) {
    int node = blockIdx.x * blockDim.y + threadIdx.y;
    if (node >= NN) return;
    int f = threadIdx.x;
    float sc, sh;
    bn_coeff(stage, f, invM, gamma, beta, sc, sh);
    size_t idx = (size_t)node * HD + f;
    float v = g_t2[batch[node] * HD + f];
    g_post[idx] += fmaxf(fmaf(v, sc, sh), 0.f);
}

__global__ void readout_kernel(const int* __restrict__ batch,
                               const float* __restrict__ gamma,
                               const float* __restrict__ beta,
                               int stage, float invM, float* __restrict__ out) {
    int node = blockIdx.x * blockDim.y + threadIdx.y;
    if (node >= NN) return;
    int f = threadIdx.x;
    float sc, sh;
    bn_coeff(stage, f, invM, gamma, beta, sc, sh);
    size_t idx = (size_t)node * HD + f;
    atomicAdd(&out[batch[node] * HD + f], fmaf(g_h[idx], sc, sh));
}

__global__ void div_kernel(float* __restrict__ out) {
    int i = blockIdx.x * blockDim.x + threadIdx.x;
    if (i < NG * HD) out[i] /= fmaxf(g_counts[i / HD], 1.0f);
}

// ---------------- launch ----------------
extern "C" void kernel_launch(void* const* d_in, const int* in_sizes, int n_in,
                              void* d_out, int out_size) {
    const float* x      = (const float*)d_in[0];
    const int*   edge   = (const int*)d_in[1];
    const int*   batch  = (const int*)d_in[2];
    const float* vn     = (const float*)d_in[4];
    const float* c1_W1  = (const float*)d_in[5];
    const float* c1_b1  = (const float*)d_in[6];
    const float* c1_g1  = (const float*)d_in[7];
    const float* c1_be1 = (const float*)d_in[8];
    const float* c1_W2  = (const float*)d_in[9];
    const float* c1_b2  = (const float*)d_in[10];
    const float* bn1_g  = (const float*)d_in[11];
    const float* bn1_b  = (const float*)d_in[12];
    const float* cs_W1  = (const float*)d_in[13];
    const float* cs_b1  = (const float*)d_in[14];
    const float* cs_g1  = (const float*)d_in[15];
    const float* cs_be1 = (const float*)d_in[16];
    const float* cs_W2  = (const float*)d_in[17];
    const float* cs_b2  = (const float*)d_in[18];
    const float* bns_g  = (const float*)d_in[19];
    const float* bns_b  = (const float*)d_in[20];
    const float* vm_W1  = (const float*)d_in[21];
    const float* vm_b1  = (const float*)d_in[22];
    const float* vm_g1  = (const float*)d_in[23];
    const float* vm_be1 = (const float*)d_in[24];
    const float* vm_W2  = (const float*)d_in[25];
    const float* vm_b2  = (const float*)d_in[26];
    const float* vm_g2  = (const float*)d_in[27];
    const float* vm_be2 = (const float*)d_in[28];
    float* out = (float*)d_out;

    const int* src = edge;
    const int* dst = edge + NE;

    float *p_agg, *p_z, *p_h, *p_post, *p_pooled, *p_t1, *p_t2;
    cudaGetSymbolAddress((void**)&p_agg, g_agg);
    cudaGetSymbolAddress((void**)&p_z, g_z);
    cudaGetSymbolAddress((void**)&p_h, g_h);
    cudaGetSymbolAddress((void**)&p_post, g_post);
    cudaGetSymbolAddress((void**)&p_pooled, g_pooled);
    cudaGetSymbolAddress((void**)&p_t1, g_t1);
    cudaGetSymbolAddress((void**)&p_t2, g_t2);

    dim3 ew(96, 4);
    int ewg = (NN + 3) / 4;
    const float invN = 1.0f / (float)NN;
    const float invG = 1.0f / (float)NG;
    int aggGrid = (NN * 32 + 255) / 256;   // warp per node

    auto g64 = [](int M) { return dim3((M + 127) / 128, DHD / 64); };  // TN=4 (NC=192)
    auto g96 = [](int M) { return dim3((M + 127) / 128, 1); };         // TN=6 (NC=96, 1 col block)

    // ---- init + CSR build ----
    zero_all_kernel<<<SCAN_BLOCKS, 1024>>>(out);
    counts_hist_kernel<<<(NE + 255) / 256, 256>>>(batch, dst);
    scan1_kernel<<<SCAN_BLOCKS, 1024>>>();
    scan3_kernel<<<SCAN_BLOCKS, 1024>>>();
    scatter_kernel<<<(NE + 255) / 256, 256>>>(src, dst);

    // ---- layer 1 (conv1 on x); stats stages 0 (z1), 1 (h1) ----
    agg_csr_kernel<<<aggGrid, 256>>>(x);
    gemm2_kernel<0, 4><<<g64(NN), 256>>>(p_agg, c1_W1, c1_b1, p_z, NN, HD, DHD,
                                         nullptr, nullptr, 0, 0.f, 0, nullptr);
    gemm2_kernel<2, 6><<<g96(NN), 256>>>(p_z, c1_W2, c1_b2, p_h, NN, DHD, HD,
                                         c1_g1, c1_be1, 0, invN, 1, nullptr);

    // ---- layer 2 (cs[0]); post1 fused into agg transform; stages 2 (z2), 3 (h2) ----
    agg_bn_kernel<<<aggGrid, 256>>>(p_h, bn1_g, bn1_b, vn, 1, invN);
    gemm2_kernel<0, 4><<<g64(NN), 256>>>(p_agg, cs_W1, cs_b1, p_z, NN, HD, DHD,
                                         nullptr, nullptr, 0, 0.f, 2, nullptr);
    gemm2_kernel<2, 6><<<g96(NN), 256>>>(p_z, cs_W2, cs_b2, p_h, NN, DHD, HD,
                                         cs_g1, cs_be1, 2, invN, 3, nullptr);
    post2_kernel<<<ewg, ew>>>(batch, bns_g, bns_b, 3, invN);

    // ---- virtual node MLP; vin fused (AMODE 3); stages 4 (t1), 5 (t2) ----
    gemm2_kernel<3, 4><<<g64(NG), 256>>>(p_pooled, vm_W1, vm_b1, p_t1, NG, HD, DHD,
                                         nullptr, nullptr, 0, 0.f, 4, vn);
    gemm2_kernel<2, 6><<<g96(NG), 256>>>(p_t1, vm_W2, vm_b2, p_t2, NG, DHD, HD,
                                         vm_g1, vm_be1, 4, invG, 5, nullptr);
    post3_kernel<<<ewg, ew>>>(batch, vm_g2, vm_be2, 5, invG);

    // ---- layer 3 (cs[1]); stages 6 (z3), 7 (h3) ----
    agg_csr_kernel<<<aggGrid, 256>>>(p_post);
    gemm2_kernel<0, 4><<<g64(NN), 256>>>(p_agg, cs_W1 + HD * DHD, cs_b1 + DHD,
                                         p_z, NN, HD, DHD,
                                         nullptr, nullptr, 0, 0.f, 6, nullptr);
    gemm2_kernel<2, 6><<<g96(NN), 256>>>(p_z, cs_W2 + DHD * HD, cs_b2 + HD,
                                         p_h, NN, DHD, HD,
                                         cs_g1 + DHD, cs_be1 + DHD, 6, invN, 7, nullptr);

    // ---- mean-pool readout ----
    readout_kernel<<<ewg, ew>>>(batch, bns_g + HD, bns_b + HD, 7, invN, out);
    div_kernel<<<(NG * HD + 255) / 256, 256>>>(out);
}